// round 1
// baseline (speedup 1.0000x reference)
#include <cuda_runtime.h>
#include <math.h>

#define BB 4
#define HH 544
#define WW 960
#define H2 272
#define W2 480
#define MD 24

// ---------------- scratch (no allocations allowed) ----------------
__device__ float g_lg[BB * H2 * W2];
__device__ float g_rg[BB * H2 * W2];
__device__ float g_nd[BB * H2 * W2];
__device__ float g_nc[BB * H2 * W2];
__device__ float g_warp[BB * 3 * HH * WW];
__device__ double g_acc[16];
// acc indices: 0 gtNum 1 gtDen 2 photoNum 3 photoDen 4 signSum 5 magSum 6 activeSum 7 smx 8 smy

// ---------------- helpers ----------------
__device__ __forceinline__ float blockReduceSum(float v, float* sbuf) {
    int tid = threadIdx.x + threadIdx.y * blockDim.x;
    int lane = tid & 31, wid = tid >> 5;
#pragma unroll
    for (int o = 16; o > 0; o >>= 1) v += __shfl_down_sync(0xffffffffu, v, o);
    if (lane == 0) sbuf[wid] = v;
    __syncthreads();
    int nw = (blockDim.x * blockDim.y + 31) >> 5;
    v = (tid < nw) ? sbuf[tid] : 0.f;
    if (wid == 0) {
#pragma unroll
        for (int o = 16; o > 0; o >>= 1) v += __shfl_down_sync(0xffffffffu, v, o);
    }
    __syncthreads();
    return v;  // valid at tid 0
}

// ---------------- kernels ----------------
__global__ void zero_kernel() {
    if (threadIdx.x < 16) g_acc[threadIdx.x] = 0.0;
}

// half-res grayscale: avg_pool(2,2) per channel then channel mean
__global__ void downsample_kernel(const float* __restrict__ left,
                                  const float* __restrict__ right) {
    int i = blockIdx.x * blockDim.x + threadIdx.x;
    if (i >= BB * H2 * W2) return;
    int x = i % W2;
    int y = (i / W2) % H2;
    int b = i / (W2 * H2);
    float sl = 0.f, sr = 0.f;
#pragma unroll
    for (int c = 0; c < 3; c++) {
        int base = ((b * 3 + c) * HH + 2 * y) * WW + 2 * x;
        sl += (left[base] + left[base + 1] + left[base + WW] + left[base + WW + 1]) * 0.25f;
        sr += (right[base] + right[base + 1] + right[base + WW] + right[base + WW + 1]) * 0.25f;
    }
    g_lg[i] = sl * (1.f / 3.f);
    g_rg[i] = sr * (1.f / 3.f);
}

// NCC disparity search: one CTA per (b, half-res row), 480 threads (one per column)
__global__ __launch_bounds__(480) void ncc_kernel() {
    __shared__ float rgS[11][528];                       // rg rows, zero-padded +/-24
    __shared__ float crp[560], cr2p[560];                // rg column sums, padded +/-40
    __shared__ float clp[560], cl2p[560];                // lg column sums, padded +/-40
    __shared__ float HcrS[528], Hcr2S[528];              // 11-box of crp at u in [-24,503]
    __shared__ float ccS[496];                           // cross column sums, padded +/-8
    const float NORM = 1.0f / 121.0f;

    int row = blockIdx.x;
    int b = row / H2;
    int y = row - b * H2;
    int x = threadIdx.x;
    const float* lgB = g_lg + b * H2 * W2;
    const float* rgB = g_rg + b * H2 * W2;

    float lgR[11];
    float cr = 0.f, cr2 = 0.f, cl = 0.f, cl2 = 0.f;
#pragma unroll
    for (int r = 0; r < 11; r++) {
        int yy = y + r - 5;
        float lv = 0.f, rv = 0.f;
        if (yy >= 0 && yy < H2) {
            lv = lgB[yy * W2 + x];
            rv = rgB[yy * W2 + x];
        }
        lgR[r] = lv;
        rgS[r][x + 24] = rv;
        if (x < 24) { rgS[r][x] = 0.f; rgS[r][x + 504] = 0.f; }
        cr += rv; cr2 += rv * rv;
        cl += lv; cl2 += lv * lv;
    }
    crp[x + 40] = cr;  cr2p[x + 40] = cr2;
    clp[x + 40] = cl;  cl2p[x + 40] = cl2;
    if (x < 40)  { crp[x] = 0.f; cr2p[x] = 0.f; clp[x] = 0.f; cl2p[x] = 0.f; }
    if (x >= 440){ crp[x + 80] = 0.f; cr2p[x + 80] = 0.f; clp[x + 80] = 0.f; cl2p[x + 80] = 0.f; }
    if (x < 8)   { ccS[x] = 0.f; ccS[488 + x] = 0.f; }
    __syncthreads();

    // horizontal 11-box of the rg column sums: Hcr(u)=sum_{k=-5..5} crp[u+k], u = x-24 (+ tail)
    {
        float s = 0.f, s2 = 0.f;
#pragma unroll
        for (int k = -5; k <= 5; k++) { s += crp[x + 16 + k]; s2 += cr2p[x + 16 + k]; }
        HcrS[x] = s; Hcr2S[x] = s2;
        if (x < 48) {
            float t = 0.f, t2 = 0.f;
#pragma unroll
            for (int k = -5; k <= 5; k++) { t += crp[x + 496 + k]; t2 += cr2p[x + 496 + k]; }
            HcrS[x + 480] = t; Hcr2S[x + 480] = t2;
        }
    }
    // left stats lm, ls (pool zero-padding handled by padded arrays)
    float lm = 0.f, lq = 0.f;
#pragma unroll
    for (int k = -5; k <= 5; k++) { lm += clp[x + 40 + k]; lq += cl2p[x + 40 + k]; }
    lm *= NORM; lq *= NORM;
    float ls = sqrtf(fmaxf(lq - lm * lm, 1e-8f));
    __syncthreads();

    float bestC = -1.0f, bestD = 0.0f;
    bool interior = (x >= 5 && x < 475);
    for (int d = -MD; d <= MD; d++) {
        if (d == 0) continue;
        // vertical cross column sum for this shift (rgS zero-padding = shift mask)
        float cc = 0.f;
#pragma unroll
        for (int r = 0; r < 11; r++) cc += lgR[r] * rgS[r][x + d + 24];
        __syncthreads();
        ccS[x + 8] = cc;
        __syncthreads();
        float cross121 = 0.f;
#pragma unroll
        for (int k = -5; k <= 5; k++) cross121 += ccS[x + 8 + k];

        float rm121, r2121;
        if (interior) {
            rm121 = HcrS[x + d + 24];
            r2121 = Hcr2S[x + d + 24];
        } else {
            rm121 = 0.f; r2121 = 0.f;
#pragma unroll
            for (int k = -5; k <= 5; k++) {
                int u = x + k;
                if (u >= 0 && u < W2) {
                    rm121 += crp[u + d + 40];
                    r2121 += cr2p[u + d + 40];
                }
            }
        }
        float rm = rm121 * NORM;
        float rstd = sqrtf(fmaxf(r2121 * NORM - rm * rm, 1e-8f));
        float ncc = (cross121 * NORM - lm * rm) / (ls * rstd + 1e-8f);
        if (ncc > bestC) { bestC = ncc; bestD = (float)d; }
    }
    int o = (b * H2 + y) * W2 + x;
    g_nd[o] = bestD * 2.0f;              // * DS
    g_nc[o] = fmaxf(bestC, 0.f);
}

// warp right image by disparity (grid_sample align_corners=True, border padding)
__global__ void warp_kernel(const float* __restrict__ pred,
                            const float* __restrict__ right) {
    int i = blockIdx.x * blockDim.x + threadIdx.x;
    if (i >= BB * 3 * HH * WW) return;
    int x = i % WW;
    int y = (i / WW) % HH;
    int c = (i / (WW * HH)) % 3;
    int b = i / (WW * HH * 3);
    float disp = pred[(b * HH + y) * WW + x];
    float xs = (float)x - disp;
    float xc = fminf(fmaxf(xs, 0.f), (float)(WW - 1));
    float x0 = floorf(xc);
    float w = xc - x0;
    int x0i = (int)x0;
    int x1i = min(x0i + 1, WW - 1);
    const float* R = right + ((b * 3 + c) * HH + y) * WW;
    g_warp[i] = R[x0i] * (1.f - w) + R[x1i] * w;
}

// SSIM(3x3 zero-padded avg pools) + L1, masked photometric mean
__global__ void photo_kernel(const float* __restrict__ left,
                             const float* __restrict__ pred) {
    __shared__ float lS[3][10][34];
    __shared__ float wS[3][10][34];
    __shared__ float sbuf[8];
    int b = blockIdx.z;
    int tx0 = blockIdx.x * 32, ty0 = blockIdx.y * 8;
    int tid = threadIdx.y * 32 + threadIdx.x;
    for (int i = tid; i < 3 * 10 * 34; i += 256) {
        int col = i % 34;
        int rrow = (i / 34) % 10;
        int c = i / 340;
        int gx = tx0 + col - 1, gy = ty0 + rrow - 1;
        float lv = 0.f, wv = 0.f;
        if (gx >= 0 && gx < WW && gy >= 0 && gy < HH) {
            int idx = ((b * 3 + c) * HH + gy) * WW + gx;
            lv = left[idx];
            wv = g_warp[idx];
        }
        lS[c][rrow][col] = lv;
        wS[c][rrow][col] = wv;
    }
    __syncthreads();

    int gx = tx0 + threadIdx.x, gy = ty0 + threadIdx.y;
    float ssSum = 0.f, l1Sum = 0.f;
    const float N9 = 1.f / 9.f;
    const float C1 = 1e-4f, C2 = 9e-4f;
#pragma unroll
    for (int c = 0; c < 3; c++) {
        float sx = 0.f, sy = 0.f, sxx = 0.f, syy = 0.f, sxy = 0.f;
#pragma unroll
        for (int dy = 0; dy < 3; dy++)
#pragma unroll
            for (int dx = 0; dx < 3; dx++) {
                float xv = lS[c][threadIdx.y + dy][threadIdx.x + dx];
                float yv = wS[c][threadIdx.y + dy][threadIdx.x + dx];
                sx += xv; sy += yv;
                sxx += xv * xv; syy += yv * yv; sxy += xv * yv;
            }
        float mx = sx * N9, my = sy * N9;
        float vx = fmaxf(sxx * N9 - mx * mx, 0.f);
        float vy = fmaxf(syy * N9 - my * my, 0.f);
        float cxy = sxy * N9 - mx * my;
        float nn = (2.f * mx * my + C1) * (2.f * cxy + C2);
        float dd = (mx * mx + my * my + C1) * (vx + vy + C2);
        float ss = fminf(fmaxf((1.f - nn / dd) * 0.5f, 0.f), 1.f);
        ssSum += ss;
        l1Sum += fabsf(lS[c][threadIdx.y + 1][threadIdx.x + 1] -
                       wS[c][threadIdx.y + 1][threadIdx.x + 1]);
    }
    float disp = pred[(b * HH + gy) * WW + gx];
    float xs = (float)gx - disp;
    float valid = (xs > 0.f && xs < (float)(WW - 1)) ? 1.f : 0.f;
    float err = 0.85f * (ssSum * (1.f / 3.f)) + 0.15f * (l1Sum * (1.f / 3.f));

    float s0 = blockReduceSum(err * valid, sbuf);
    float s1 = blockReduceSum(valid, sbuf);
    if (tid == 0) {
        atomicAdd(&g_acc[2], (double)s0);
        atomicAdd(&g_acc[3], (double)s1);
    }
}

// GT anchor + smoothness + sign/magnitude, one full-res pass
__global__ void fullres_kernel(const float* __restrict__ pred,
                               const float* __restrict__ gt,
                               const float* __restrict__ conf,
                               const float* __restrict__ occ,
                               const float* __restrict__ left) {
    __shared__ float sbuf[8];
    const int total = BB * HH * WW;
    float a_gtn = 0.f, a_gtd = 0.f, a_sx = 0.f, a_sy = 0.f;
    float a_sign = 0.f, a_mag = 0.f, a_act = 0.f;
    for (int i = blockIdx.x * blockDim.x + threadIdx.x; i < total;
         i += gridDim.x * blockDim.x) {
        int x = i % WW;
        int y = (i / WW) % HH;
        int b = i / (WW * HH);
        float p = pred[i];
        float g = gt[i];
        float trust = (g > 2.f) ? conf[i] * occ[i] : 0.f;
        a_gtn += trust * fabsf(p - g);
        a_gtd += trust;

        const float* Lb = left + b * 3 * HH * WW;
        int r0 = y * WW + x;
        if (x < WW - 1) {
            float ddx = fabsf(pred[i + 1] - p);
            float idx = (fabsf(Lb[r0 + 1] - Lb[r0]) +
                         fabsf(Lb[HH * WW + r0 + 1] - Lb[HH * WW + r0]) +
                         fabsf(Lb[2 * HH * WW + r0 + 1] - Lb[2 * HH * WW + r0])) * (1.f / 3.f);
            a_sx += ddx * expf(-idx);
        }
        if (y < HH - 1) {
            float ddy = fabsf(pred[i + WW] - p);
            float idy = (fabsf(Lb[r0 + WW] - Lb[r0]) +
                         fabsf(Lb[HH * WW + r0 + WW] - Lb[HH * WW + r0]) +
                         fabsf(Lb[2 * HH * WW + r0 + WW] - Lb[2 * HH * WW + r0])) * (1.f / 3.f);
            a_sy += ddy * expf(-idy);
        }

        int hid = (b * H2 + (y >> 1)) * W2 + (x >> 1);
        float ncv = g_nc[hid];
        if (ncv > 0.3f) {
            float ndv = g_nd[hid];
            a_act += 1.f;
            float s = (ndv > 0.f) ? 1.f : ((ndv < 0.f) ? -1.f : 0.f);
            a_sign += fmaxf(-p * s, 0.f);
            a_mag += ncv * fabsf(p - ndv);
        }
    }
    float v;
    v = blockReduceSum(a_gtn, sbuf);  if (threadIdx.x == 0) atomicAdd(&g_acc[0], (double)v);
    v = blockReduceSum(a_gtd, sbuf);  if (threadIdx.x == 0) atomicAdd(&g_acc[1], (double)v);
    v = blockReduceSum(a_sign, sbuf); if (threadIdx.x == 0) atomicAdd(&g_acc[4], (double)v);
    v = blockReduceSum(a_mag, sbuf);  if (threadIdx.x == 0) atomicAdd(&g_acc[5], (double)v);
    v = blockReduceSum(a_act, sbuf);  if (threadIdx.x == 0) atomicAdd(&g_acc[6], (double)v);
    v = blockReduceSum(a_sx, sbuf);   if (threadIdx.x == 0) atomicAdd(&g_acc[7], (double)v);
    v = blockReduceSum(a_sy, sbuf);   if (threadIdx.x == 0) atomicAdd(&g_acc[8], (double)v);
}

__global__ void finalize_kernel(float* __restrict__ out) {
    double gtl = g_acc[0] / fmax(g_acc[1], 1.0);
    double photo = g_acc[2] / fmax(g_acc[3], 1.0);
    double n = fmax(g_acc[6], 1.0);
    double signmag = 0.3 * (g_acc[4] / n) + 0.7 * (g_acc[5] / n);
    double smooth = g_acc[7] / ((double)BB * HH * (WW - 1)) +
                    g_acc[8] / ((double)BB * (HH - 1) * WW);
    out[0] = (float)(1.0 * gtl + 1.0 * photo + 0.5 * signmag + 0.1 * smooth);
}

// ---------------- launch ----------------
extern "C" void kernel_launch(void* const* d_in, const int* in_sizes, int n_in,
                              void* d_out, int out_size) {
    const float* pred  = (const float*)d_in[0];
    const float* gt    = (const float*)d_in[1];
    const float* conf  = (const float*)d_in[2];
    const float* occ   = (const float*)d_in[3];
    const float* left  = (const float*)d_in[4];
    const float* right = (const float*)d_in[5];
    float* out = (float*)d_out;

    zero_kernel<<<1, 32>>>();
    downsample_kernel<<<(BB * H2 * W2 + 255) / 256, 256>>>(left, right);
    ncc_kernel<<<BB * H2, 480>>>();
    warp_kernel<<<(BB * 3 * HH * WW + 255) / 256, 256>>>(pred, right);
    dim3 pb(32, 8), pg(WW / 32, HH / 8, BB);
    photo_kernel<<<pg, pb>>>(left, pred);
    fullres_kernel<<<2048, 256>>>(pred, gt, conf, occ, left);
    finalize_kernel<<<1, 1>>>(out);
}

// round 2
// speedup vs baseline: 1.1743x; 1.1743x over previous
#include <cuda_runtime.h>
#include <math.h>

#define BB 4
#define HH 544
#define WW 960
#define H2 272
#define W2 480
#define MD 24

// ---------------- scratch (no allocations allowed) ----------------
__device__ float g_lg[BB * H2 * W2];
__device__ float g_rg[BB * H2 * W2];
__device__ float g_nd[BB * H2 * W2];
__device__ float g_nc[BB * H2 * W2];
// accumulators padded to one 128B line each to avoid LTS atomic serialization
// idx: 0 gtNum 1 gtDen 2 photoNum 3 photoDen 4 signSum 5 magSum 6 activeSum 7 smx 8 smy
__device__ double g_acc[9 * 16];

// ---------------- helpers ----------------
__device__ __forceinline__ float blockReduceSum(float v, float* sbuf) {
    int tid = threadIdx.x + threadIdx.y * blockDim.x;
    int lane = tid & 31, wid = tid >> 5;
#pragma unroll
    for (int o = 16; o > 0; o >>= 1) v += __shfl_down_sync(0xffffffffu, v, o);
    if (lane == 0) sbuf[wid] = v;
    __syncthreads();
    int nw = (blockDim.x * blockDim.y + 31) >> 5;
    v = (tid < nw) ? sbuf[tid] : 0.f;
    if (wid == 0) {
#pragma unroll
        for (int o = 16; o > 0; o >>= 1) v += __shfl_down_sync(0xffffffffu, v, o);
    }
    __syncthreads();
    return v;  // valid at tid 0
}

// ---------------- kernels ----------------
__global__ void zero_kernel() {
    int t = threadIdx.x;
    if (t < 9 * 16) g_acc[t] = 0.0;
}

// half-res grayscale: avg_pool(2,2) per channel then channel mean (float4 loads, 2 outputs/thread)
__global__ void downsample_kernel(const float* __restrict__ left,
                                  const float* __restrict__ right) {
    int i = blockIdx.x * blockDim.x + threadIdx.x;
    const int NPAIR = W2 / 2;  // 240
    if (i >= BB * H2 * NPAIR) return;
    int px = i % NPAIR;
    int y = (i / NPAIR) % H2;
    int b = i / (NPAIR * H2);
    float l0 = 0.f, l1 = 0.f, r0 = 0.f, r1 = 0.f;
#pragma unroll
    for (int c = 0; c < 3; c++) {
        int base = ((b * 3 + c) * HH + 2 * y) * WW + 4 * px;
        float4 a0 = *(const float4*)(left + base);
        float4 a1 = *(const float4*)(left + base + WW);
        l0 += (a0.x + a0.y + a1.x + a1.y);
        l1 += (a0.z + a0.w + a1.z + a1.w);
        float4 b0 = *(const float4*)(right + base);
        float4 b1 = *(const float4*)(right + base + WW);
        r0 += (b0.x + b0.y + b1.x + b1.y);
        r1 += (b0.z + b0.w + b1.z + b1.w);
    }
    const float S = 0.25f / 3.0f;
    int o = (b * H2 + y) * W2 + 2 * px;
    *(float2*)(g_lg + o) = make_float2(l0 * S, l1 * S);
    *(float2*)(g_rg + o) = make_float2(r0 * S, r1 * S);
}

// NCC disparity search: one CTA per (b, half-res row), 480 threads (one per column)
// disparities processed in groups of 6 -> 2 syncs per group (16 total vs 96)
__global__ __launch_bounds__(480) void ncc_kernel() {
    __shared__ float rgS[11][528];                       // rg rows, zero-padded +/-24
    __shared__ float crp[560], cr2p[560];                // rg column sums, padded +/-40
    __shared__ float clp[560], cl2p[560];                // lg column sums, padded +/-40
    __shared__ float HcrS[528], Hcr2S[528];              // 11-box of crp at u in [-24,503]
    __shared__ float ccS[6][496];                        // cross column sums per group, padded +/-8
    const float NORM = 1.0f / 121.0f;

    int row = blockIdx.x;
    int b = row / H2;
    int y = row - b * H2;
    int x = threadIdx.x;
    const float* lgB = g_lg + b * H2 * W2;
    const float* rgB = g_rg + b * H2 * W2;

    float lgR[11];
    float cr = 0.f, cr2 = 0.f, cl = 0.f, cl2 = 0.f;
#pragma unroll
    for (int r = 0; r < 11; r++) {
        int yy = y + r - 5;
        float lv = 0.f, rv = 0.f;
        if (yy >= 0 && yy < H2) {
            lv = lgB[yy * W2 + x];
            rv = rgB[yy * W2 + x];
        }
        lgR[r] = lv;
        rgS[r][x + 24] = rv;
        if (x < 24) { rgS[r][x] = 0.f; rgS[r][x + 504] = 0.f; }
        cr += rv; cr2 += rv * rv;
        cl += lv; cl2 += lv * lv;
    }
    crp[x + 40] = cr;  cr2p[x + 40] = cr2;
    clp[x + 40] = cl;  cl2p[x + 40] = cl2;
    if (x < 40)  { crp[x] = 0.f; cr2p[x] = 0.f; clp[x] = 0.f; cl2p[x] = 0.f; }
    if (x >= 440){ crp[x + 80] = 0.f; cr2p[x + 80] = 0.f; clp[x + 80] = 0.f; cl2p[x + 80] = 0.f; }
    if (x < 8) {
#pragma unroll
        for (int j = 0; j < 6; j++) { ccS[j][x] = 0.f; ccS[j][488 + x] = 0.f; }
    }
    __syncthreads();

    // horizontal 11-box of the rg column sums: Hcr(u)=sum_{k=-5..5} crp[u+k], u = x-24 (+ tail)
    {
        float s = 0.f, s2 = 0.f;
#pragma unroll
        for (int k = -5; k <= 5; k++) { s += crp[x + 16 + k]; s2 += cr2p[x + 16 + k]; }
        HcrS[x] = s; Hcr2S[x] = s2;
        if (x < 48) {
            float t = 0.f, t2 = 0.f;
#pragma unroll
            for (int k = -5; k <= 5; k++) { t += crp[x + 496 + k]; t2 += cr2p[x + 496 + k]; }
            HcrS[x + 480] = t; Hcr2S[x + 480] = t2;
        }
    }
    // left stats lm, ls
    float lm = 0.f, lq = 0.f;
#pragma unroll
    for (int k = -5; k <= 5; k++) { lm += clp[x + 40 + k]; lq += cl2p[x + 40 + k]; }
    lm *= NORM; lq *= NORM;
    float ls = sqrtf(fmaxf(lq - lm * lm, 1e-8f));
    __syncthreads();

    float bestC = -1.0f, bestD = 0.0f;
    bool interior = (x >= 5 && x < 475);
    for (int g = 0; g < 8; g++) {
        float cc[6];
#pragma unroll
        for (int j = 0; j < 6; j++) {
            int idx = g * 6 + j;
            int d = (idx < 24) ? (idx - 24) : (idx - 23);
            float s = 0.f;
#pragma unroll
            for (int r = 0; r < 11; r++) s += lgR[r] * rgS[r][x + d + 24];
            cc[j] = s;
        }
#pragma unroll
        for (int j = 0; j < 6; j++) ccS[j][x + 8] = cc[j];
        __syncthreads();
#pragma unroll
        for (int j = 0; j < 6; j++) {
            int idx = g * 6 + j;
            int d = (idx < 24) ? (idx - 24) : (idx - 23);
            float cross121 = 0.f;
#pragma unroll
            for (int k = -5; k <= 5; k++) cross121 += ccS[j][x + 8 + k];
            float rm121, r2121;
            if (interior) {
                rm121 = HcrS[x + d + 24];
                r2121 = Hcr2S[x + d + 24];
            } else {
                rm121 = 0.f; r2121 = 0.f;
#pragma unroll
                for (int k = -5; k <= 5; k++) {
                    int u = x + k;
                    if (u >= 0 && u < W2) {
                        rm121 += crp[u + d + 40];
                        r2121 += cr2p[u + d + 40];
                    }
                }
            }
            float rm = rm121 * NORM;
            float rstd = sqrtf(fmaxf(r2121 * NORM - rm * rm, 1e-8f));
            float ncc = (cross121 * NORM - lm * rm) / (ls * rstd + 1e-8f);
            if (ncc > bestC) { bestC = ncc; bestD = (float)d; }
        }
        __syncthreads();
    }
    int o = (b * H2 + y) * W2 + x;
    g_nd[o] = bestD * 2.0f;
    g_nc[o] = fmaxf(bestC, 0.f);
}

// ONE fused full-res pass: warp-on-the-fly + SSIM/L1 photometric + GT anchor
// + smoothness + sign/magnitude. 32x8 tiles with 1-px halo in smem.
__global__ void tile_kernel(const float* __restrict__ pred,
                            const float* __restrict__ gt,
                            const float* __restrict__ conf,
                            const float* __restrict__ occ,
                            const float* __restrict__ left,
                            const float* __restrict__ right) {
    __shared__ float lS[3][10][34];
    __shared__ float wS[3][10][34];
    __shared__ float dS[10][34];
    __shared__ float sbuf[8];
    int b = blockIdx.z;
    int tx0 = blockIdx.x * 32, ty0 = blockIdx.y * 8;
    int tid = threadIdx.y * 32 + threadIdx.x;

    // halo load: compute warped right on the fly
    for (int i = tid; i < 10 * 34; i += 256) {
        int col = i % 34;
        int rrow = i / 34;
        int gx = tx0 + col - 1, gy = ty0 + rrow - 1;
        if (gx >= 0 && gx < WW && gy >= 0 && gy < HH) {
            float disp = pred[(b * HH + gy) * WW + gx];
            dS[rrow][col] = disp;
            float xs = (float)gx - disp;
            float xc = fminf(fmaxf(xs, 0.f), (float)(WW - 1));
            float x0 = floorf(xc);
            float w = xc - x0;
            int x0i = (int)x0;
            int x1i = min(x0i + 1, WW - 1);
#pragma unroll
            for (int c = 0; c < 3; c++) {
                const float* R = right + ((b * 3 + c) * HH + gy) * WW;
                wS[c][rrow][col] = R[x0i] * (1.f - w) + R[x1i] * w;
                lS[c][rrow][col] = left[((b * 3 + c) * HH + gy) * WW + gx];
            }
        } else {
            dS[rrow][col] = 0.f;
#pragma unroll
            for (int c = 0; c < 3; c++) { wS[c][rrow][col] = 0.f; lS[c][rrow][col] = 0.f; }
        }
    }
    __syncthreads();

    int tx = threadIdx.x, ty = threadIdx.y;
    int gx = tx0 + tx, gy = ty0 + ty;

    // --- photometric (SSIM 3x3 zero-padded pools + L1) ---
    float ssSum = 0.f, l1Sum = 0.f;
    const float N9 = 1.f / 9.f;
    const float C1 = 1e-4f, C2 = 9e-4f;
#pragma unroll
    for (int c = 0; c < 3; c++) {
        float sx = 0.f, sy = 0.f, sxx = 0.f, syy = 0.f, sxy = 0.f;
#pragma unroll
        for (int dy = 0; dy < 3; dy++)
#pragma unroll
            for (int dx = 0; dx < 3; dx++) {
                float xv = lS[c][ty + dy][tx + dx];
                float yv = wS[c][ty + dy][tx + dx];
                sx += xv; sy += yv;
                sxx += xv * xv; syy += yv * yv; sxy += xv * yv;
            }
        float mx = sx * N9, my = sy * N9;
        float vx = fmaxf(sxx * N9 - mx * mx, 0.f);
        float vy = fmaxf(syy * N9 - my * my, 0.f);
        float cxy = sxy * N9 - mx * my;
        float nn = (2.f * mx * my + C1) * (2.f * cxy + C2);
        float dd = (mx * mx + my * my + C1) * (vx + vy + C2);
        float ss = fminf(fmaxf((1.f - nn / dd) * 0.5f, 0.f), 1.f);
        ssSum += ss;
        l1Sum += fabsf(lS[c][ty + 1][tx + 1] - wS[c][ty + 1][tx + 1]);
    }
    float dcen = dS[ty + 1][tx + 1];
    float xs = (float)gx - dcen;
    float valid = (xs > 0.f && xs < (float)(WW - 1)) ? 1.f : 0.f;
    float perr = (0.85f * (ssSum * (1.f / 3.f)) + 0.15f * (l1Sum * (1.f / 3.f))) * valid;

    // --- GT anchor ---
    int gi = (b * HH + gy) * WW + gx;
    float g = gt[gi];
    float trust = (g > 2.f) ? conf[gi] * occ[gi] : 0.f;
    float gtn = trust * fabsf(dcen - g);

    // --- smoothness (uses halo smem) ---
    float a_sx = 0.f, a_sy = 0.f;
    if (gx < WW - 1) {
        float ddx = fabsf(dS[ty + 1][tx + 2] - dcen);
        float idx = (fabsf(lS[0][ty + 1][tx + 2] - lS[0][ty + 1][tx + 1]) +
                     fabsf(lS[1][ty + 1][tx + 2] - lS[1][ty + 1][tx + 1]) +
                     fabsf(lS[2][ty + 1][tx + 2] - lS[2][ty + 1][tx + 1])) * (1.f / 3.f);
        a_sx = ddx * __expf(-idx);
    }
    if (gy < HH - 1) {
        float ddy = fabsf(dS[ty + 2][tx + 1] - dcen);
        float idy = (fabsf(lS[0][ty + 2][tx + 1] - lS[0][ty + 1][tx + 1]) +
                     fabsf(lS[1][ty + 2][tx + 1] - lS[1][ty + 1][tx + 1]) +
                     fabsf(lS[2][ty + 2][tx + 1] - lS[2][ty + 1][tx + 1])) * (1.f / 3.f);
        a_sy = ddy * __expf(-idy);
    }

    // --- sign / magnitude from NCC maps (nearest upsample = index >>1) ---
    float a_sign = 0.f, a_mag = 0.f, a_act = 0.f;
    {
        int hid = (b * H2 + (gy >> 1)) * W2 + (gx >> 1);
        float ncv = g_nc[hid];
        if (ncv > 0.3f) {
            float ndv = g_nd[hid];
            a_act = 1.f;
            float s = (ndv > 0.f) ? 1.f : ((ndv < 0.f) ? -1.f : 0.f);
            a_sign = fmaxf(-dcen * s, 0.f);
            a_mag = ncv * fabsf(dcen - ndv);
        }
    }

    __syncthreads();
    float v;
    v = blockReduceSum(gtn, sbuf);    if (tid == 0) atomicAdd(&g_acc[0 * 16], (double)v);
    v = blockReduceSum(trust, sbuf);  if (tid == 0) atomicAdd(&g_acc[1 * 16], (double)v);
    v = blockReduceSum(perr, sbuf);   if (tid == 0) atomicAdd(&g_acc[2 * 16], (double)v);
    v = blockReduceSum(valid, sbuf);  if (tid == 0) atomicAdd(&g_acc[3 * 16], (double)v);
    v = blockReduceSum(a_sign, sbuf); if (tid == 0) atomicAdd(&g_acc[4 * 16], (double)v);
    v = blockReduceSum(a_mag, sbuf);  if (tid == 0) atomicAdd(&g_acc[5 * 16], (double)v);
    v = blockReduceSum(a_act, sbuf);  if (tid == 0) atomicAdd(&g_acc[6 * 16], (double)v);
    v = blockReduceSum(a_sx, sbuf);   if (tid == 0) atomicAdd(&g_acc[7 * 16], (double)v);
    v = blockReduceSum(a_sy, sbuf);   if (tid == 0) atomicAdd(&g_acc[8 * 16], (double)v);
}

__global__ void finalize_kernel(float* __restrict__ out) {
    double gtl = g_acc[0 * 16] / fmax(g_acc[1 * 16], 1.0);
    double photo = g_acc[2 * 16] / fmax(g_acc[3 * 16], 1.0);
    double n = fmax(g_acc[6 * 16], 1.0);
    double signmag = 0.3 * (g_acc[4 * 16] / n) + 0.7 * (g_acc[5 * 16] / n);
    double smooth = g_acc[7 * 16] / ((double)BB * HH * (WW - 1)) +
                    g_acc[8 * 16] / ((double)BB * (HH - 1) * WW);
    out[0] = (float)(1.0 * gtl + 1.0 * photo + 0.5 * signmag + 0.1 * smooth);
}

// ---------------- launch ----------------
extern "C" void kernel_launch(void* const* d_in, const int* in_sizes, int n_in,
                              void* d_out, int out_size) {
    const float* pred  = (const float*)d_in[0];
    const float* gt    = (const float*)d_in[1];
    const float* conf  = (const float*)d_in[2];
    const float* occ   = (const float*)d_in[3];
    const float* left  = (const float*)d_in[4];
    const float* right = (const float*)d_in[5];
    float* out = (float*)d_out;

    zero_kernel<<<1, 160>>>();
    downsample_kernel<<<(BB * H2 * (W2 / 2) + 255) / 256, 256>>>(left, right);
    ncc_kernel<<<BB * H2, 480>>>();
    dim3 tb(32, 8), tg(WW / 32, HH / 8, BB);
    tile_kernel<<<tg, tb>>>(pred, gt, conf, occ, left, right);
    finalize_kernel<<<1, 1>>>(out);
}